// round 3
// baseline (speedup 1.0000x reference)
#include <cuda_runtime.h>
#include <math.h>
#include <math_constants.h>

// QuadraticLorentzAttention: causal Lorentz (Minkowski) attention.
// B*H = 32, N = 2048, D = 65 (Lorentz), fp32.
// scores = <Q', K> with Q'_0 = -Q_0; causal softmax; y = P @ V;
// out[...,0] = sqrt(||y[...,1:]||^2 + 1), out[...,1:] = y[...,1:].
//
// R1/R2: packed f32x2 FMA (FFMA2) for score + accumulator updates -> halves
// fma-pipe issue count; reversed CTA order for causal load balance.
// (R2 resubmission — prior round hit a broker infra failure.)

namespace {
constexpr int N_SEQ = 2048;
constexpr int D     = 65;
constexpr int DP    = 68;   // padded (pairs of f32 -> 34 f32x2)
constexpr int NPAIR = 34;   // DP/2
constexpr int NV    = 17;   // DP/4 (16B vectors per row)
constexpr int BQ    = 64;   // queries per block (1 per thread)
constexpr int BK    = 64;   // key tile
}

using ull = unsigned long long;

__device__ __forceinline__ ull pack2(float lo, float hi) {
    ull r; asm("mov.b64 %0, {%1, %2};" : "=l"(r) : "f"(lo), "f"(hi)); return r;
}
__device__ __forceinline__ void unpack2(ull v, float& lo, float& hi) {
    asm("mov.b64 {%0, %1}, %2;" : "=f"(lo), "=f"(hi) : "l"(v));
}
__device__ __forceinline__ ull fma2(ull a, ull b, ull c) {
    ull d; asm("fma.rn.f32x2 %0, %1, %2, %3;" : "=l"(d) : "l"(a), "l"(b), "l"(c)); return d;
}
__device__ __forceinline__ ull mul2(ull a, ull b) {
    ull d; asm("mul.rn.f32x2 %0, %1, %2;" : "=l"(d) : "l"(a), "l"(b)); return d;
}

__global__ void __launch_bounds__(BQ)
lorentz_attn_kernel(const float* __restrict__ Qg,
                    const float* __restrict__ Kg,
                    const float* __restrict__ Vg,
                    const int* __restrict__ causal_p,
                    float* __restrict__ Og)
{
    __shared__ ulonglong2 ks2[BK * NV];
    __shared__ ulonglong2 vs2[BK * NV];
    float* ksf = reinterpret_cast<float*>(ks2);
    float* vsf = reinterpret_cast<float*>(vs2);

    const int tid = threadIdx.x;
    const int bh  = blockIdx.y;
    // reversed order: heaviest causal tiles (largest kend) launch first
    const int q0  = (gridDim.x - 1 - blockIdx.x) * BQ;
    const int qi  = q0 + tid;
    const size_t base = (size_t)bh * N_SEQ * D;

    // zero pad columns (65..67) once; tile loads only touch d < 65
    ksf[tid * DP + 65] = 0.f; ksf[tid * DP + 66] = 0.f; ksf[tid * DP + 67] = 0.f;
    vsf[tid * DP + 65] = 0.f; vsf[tid * DP + 66] = 0.f; vsf[tid * DP + 67] = 0.f;

    // load query row as 34 packed pairs, time component negated
    ull q2[NPAIR];
    {
        float qr[DP];
        const float* qrow = Qg + base + (size_t)qi * D;
        #pragma unroll
        for (int d = 0; d < D; d++) qr[d] = qrow[d];
        qr[0] = -qr[0];
        qr[65] = 0.f; qr[66] = 0.f; qr[67] = 0.f;
        #pragma unroll
        for (int i = 0; i < NPAIR; i++) q2[i] = pack2(qr[2*i], qr[2*i+1]);
    }

    ull acc2[NPAIR];
    const ull zz = pack2(0.f, 0.f);
    #pragma unroll
    for (int i = 0; i < NPAIR; i++) acc2[i] = zz;
    float m = -CUDART_INF_F;
    float l = 0.f;

    const int cz = *causal_p;
    const int kend = cz ? (q0 + BQ) : N_SEQ;

    for (int k0 = 0; k0 < kend; k0 += BK) {
        __syncthreads();
        const float* kp = Kg + base + (size_t)k0 * D;
        const float* vp = Vg + base + (size_t)k0 * D;
        for (int idx = tid; idx < BK * D; idx += BQ) {
            const int r = idx / D;
            const int d = idx - r * D;
            ksf[r * DP + d] = kp[idx];
            vsf[r * DP + d] = vp[idx];
        }
        __syncthreads();

        int jmax = cz ? (qi - k0 + 1) : BK;
        if (jmax > BK) jmax = BK;

        #pragma unroll 2
        for (int j = 0; j < BK; j++) {
            // score: 2 independent f32x2 chains (4 scalar chains)
            ull sA = zz, sB = zz;
            #pragma unroll
            for (int i = 0; i < NV; i++) {
                const ulonglong2 k2 = ks2[j * NV + i];
                sA = fma2(q2[2*i + 0], k2.x, sA);
                sB = fma2(q2[2*i + 1], k2.y, sB);
            }
            float a0, a1, b0, b1;
            unpack2(sA, a0, a1);
            unpack2(sB, b0, b1);
            float s = (a0 + a1) + (b0 + b1);
            if (j >= jmax) s = -CUDART_INF_F;   // causal mask (j=0 always valid)

            const float m_new = fmaxf(m, s);
            const float p = __expf(s - m_new);
            const ull pp = pack2(p, p);

            if (__all_sync(0xffffffffu, m_new == m)) {
                // fast path: running max unchanged warp-wide -> no rescale
                l += p;
                #pragma unroll
                for (int i = 0; i < NV; i++) {
                    const ulonglong2 v2 = vs2[j * NV + i];
                    acc2[2*i + 0] = fma2(pp, v2.x, acc2[2*i + 0]);
                    acc2[2*i + 1] = fma2(pp, v2.y, acc2[2*i + 1]);
                }
            } else {
                const float corr = __expf(m - m_new);
                const ull cc = pack2(corr, corr);
                l = fmaf(l, corr, p);
                m = m_new;
                #pragma unroll
                for (int i = 0; i < NV; i++) {
                    const ulonglong2 v2 = vs2[j * NV + i];
                    acc2[2*i + 0] = fma2(acc2[2*i + 0], cc, mul2(pp, v2.x));
                    acc2[2*i + 1] = fma2(acc2[2*i + 1], cc, mul2(pp, v2.y));
                }
            }
        }
    }

    // epilogue: normalize, recompute time coordinate, write out
    const float inv_l = 1.0f / l;
    const ull il2 = pack2(inv_l, inv_l);
    float y[DP];
    #pragma unroll
    for (int i = 0; i < NPAIR; i++) {
        acc2[i] = mul2(acc2[i], il2);
        unpack2(acc2[i], y[2*i], y[2*i + 1]);
    }
    float ss = 0.f;
    #pragma unroll
    for (int d = 1; d < D; d++) ss += y[d] * y[d];
    const float t = sqrtf(ss + 1.0f);   // -1/K with K = -1

    float* orow = Og + base + (size_t)qi * D;
    orow[0] = t;
    #pragma unroll
    for (int d = 1; d < D; d++) orow[d] = y[d];
}

extern "C" void kernel_launch(void* const* d_in, const int* in_sizes, int n_in,
                              void* d_out, int out_size)
{
    const float* Q  = (const float*)d_in[0];
    const float* K  = (const float*)d_in[1];
    const float* V  = (const float*)d_in[2];
    const int* causal = (const int*)d_in[3];
    float* out = (float*)d_out;

    const int BH = in_sizes[0] / (N_SEQ * D);   // 32
    dim3 grid(N_SEQ / BQ, BH);
    dim3 block(BQ);
    lorentz_attn_kernel<<<grid, block>>>(Q, K, V, causal, out);
}

// round 4
// speedup vs baseline: 1.2565x; 1.2565x over previous
#include <cuda_runtime.h>
#include <math.h>
#include <math_constants.h>

// QuadraticLorentzAttention: causal Lorentz (Minkowski) attention.
// B*H = 32, N = 2048, D = 65 (Lorentz), fp32.
// scores = <Q', K> with Q'_0 = -Q_0; causal softmax; y = P @ V;
// out[...,0] = sqrt(||y[...,1:]||^2 + 1), out[...,1:] = y[...,1:].
//
// R3: revert f32x2 (alu-pipe regression). Split each query across 2 threads
// (36 dims each): halves dependency chains + register state, doubles
// warps/CTA. Score halves combined via shfl.bfly. Heavy-first CTA order.

namespace {
constexpr int N_SEQ  = 2048;
constexpr int D      = 65;
constexpr int DP     = 72;    // padded row: 2 halves x 36 floats (9 float4)
constexpr int HALF   = 36;
constexpr int NV     = 9;     // float4 per half
constexpr int NROW4  = DP / 4; // 18 float4 per row
constexpr int BQ     = 64;    // queries per CTA
constexpr int BK     = 64;    // key tile
constexpr int THREADS = 128;  // 2 threads per query
}

__global__ void __launch_bounds__(THREADS, 3)
lorentz_attn_kernel(const float* __restrict__ Qg,
                    const float* __restrict__ Kg,
                    const float* __restrict__ Vg,
                    const int* __restrict__ causal_p,
                    float* __restrict__ Og)
{
    __shared__ float4 ks4[BK * NROW4];
    __shared__ float4 vs4[BK * NROW4];
    float* ksf = reinterpret_cast<float*>(ks4);
    float* vsf = reinterpret_cast<float*>(vs4);

    const int tid = threadIdx.x;
    const int h   = tid & 1;        // which half of the dims
    const int ql  = tid >> 1;       // local query index (0..63)
    const int bh  = blockIdx.y;
    // reversed order: heaviest causal tiles (largest kend) launch first
    const int q0  = (gridDim.x - 1 - blockIdx.x) * BQ;
    const int qi  = q0 + ql;
    const size_t base = (size_t)bh * N_SEQ * D;

    // zero pad columns (65..71); tile loads only touch d < 65
    for (int idx = tid; idx < BK * (DP - D); idx += THREADS) {
        const int r = idx / (DP - D);
        const int c = idx - r * (DP - D);
        ksf[r * DP + D + c] = 0.f;
        vsf[r * DP + D + c] = 0.f;
    }

    // this thread's half of the query row (time component negated, pads 0)
    float q_r[HALF];
    {
        const float* qrow = Qg + base + (size_t)qi * D + h * HALF;
        const int nval = h ? (D - HALF) : HALF;   // 29 or 36
        #pragma unroll
        for (int d = 0; d < HALF; d++) q_r[d] = (d < nval) ? qrow[d] : 0.f;
        if (h == 0) q_r[0] = -q_r[0];
    }

    float acc[HALF];
    #pragma unroll
    for (int i = 0; i < HALF; i++) acc[i] = 0.f;
    float m = -CUDART_INF_F;
    float l = 0.f;

    const int cz = *causal_p;
    const int kend = cz ? (q0 + BQ) : N_SEQ;

    for (int k0 = 0; k0 < kend; k0 += BK) {
        __syncthreads();
        // rows contiguous in gmem (stride D): coalesced load, padded scatter
        const float* kp = Kg + base + (size_t)k0 * D;
        const float* vp = Vg + base + (size_t)k0 * D;
        for (int idx = tid; idx < BK * D; idx += THREADS) {
            const int r = idx / D;
            const int d = idx - r * D;
            ksf[r * DP + d] = kp[idx];
            vsf[r * DP + d] = vp[idx];
        }
        __syncthreads();

        int jmax = cz ? (qi - k0 + 1) : BK;
        if (jmax > BK) jmax = BK;

        #pragma unroll 2
        for (int j = 0; j < BK; j++) {
            // partial score over this half: 4 independent FMA chains
            float s0 = 0.f, s1 = 0.f, s2 = 0.f, s3 = 0.f;
            const float4* krow = &ks4[j * NROW4 + h * NV];
            #pragma unroll
            for (int i = 0; i < NV; i++) {
                const float4 k4 = krow[i];
                s0 = fmaf(q_r[4*i + 0], k4.x, s0);
                s1 = fmaf(q_r[4*i + 1], k4.y, s1);
                s2 = fmaf(q_r[4*i + 2], k4.z, s2);
                s3 = fmaf(q_r[4*i + 3], k4.w, s3);
            }
            const float part = (s0 + s1) + (s2 + s3);
            float s = part + __shfl_xor_sync(0xffffffffu, part, 1);
            if (j >= jmax) s = -CUDART_INF_F;   // causal mask (j=0 always valid)

            const float m_new = fmaxf(m, s);
            const float p = __expf(s - m_new);
            const float4* vrow = &vs4[j * NROW4 + h * NV];

            if (__all_sync(0xffffffffu, m_new == m)) {
                // fast path: running max unchanged warp-wide -> no rescale
                l += p;
                #pragma unroll
                for (int i = 0; i < NV; i++) {
                    const float4 v4 = vrow[i];
                    acc[4*i + 0] = fmaf(p, v4.x, acc[4*i + 0]);
                    acc[4*i + 1] = fmaf(p, v4.y, acc[4*i + 1]);
                    acc[4*i + 2] = fmaf(p, v4.z, acc[4*i + 2]);
                    acc[4*i + 3] = fmaf(p, v4.w, acc[4*i + 3]);
                }
            } else {
                const float corr = __expf(m - m_new);
                l = fmaf(l, corr, p);
                m = m_new;
                #pragma unroll
                for (int i = 0; i < NV; i++) {
                    const float4 v4 = vrow[i];
                    acc[4*i + 0] = fmaf(p, v4.x, acc[4*i + 0] * corr);
                    acc[4*i + 1] = fmaf(p, v4.y, acc[4*i + 1] * corr);
                    acc[4*i + 2] = fmaf(p, v4.z, acc[4*i + 2] * corr);
                    acc[4*i + 3] = fmaf(p, v4.w, acc[4*i + 3] * corr);
                }
            }
        }
    }

    // epilogue: normalize, recompute time coordinate, write out
    const float inv_l = 1.0f / l;
    #pragma unroll
    for (int i = 0; i < HALF; i++) acc[i] *= inv_l;

    float ssp = 0.f;
    #pragma unroll
    for (int i = 0; i < HALF; i++) ssp += acc[i] * acc[i];
    if (h == 0) ssp -= acc[0] * acc[0];     // exclude weighted time coord
    const float ss = ssp + __shfl_xor_sync(0xffffffffu, ssp, 1);
    const float t = sqrtf(ss + 1.0f);       // -1/K with K = -1

    float* orow = Og + base + (size_t)qi * D + h * HALF;
    if (h == 0) {
        orow[0] = t;
        #pragma unroll
        for (int d = 1; d < HALF; d++) orow[d] = acc[d];
    } else {
        #pragma unroll
        for (int d = 0; d < HALF; d++)
            if (d < D - HALF) orow[d] = acc[d];   // dims 36..64 only
    }
}

extern "C" void kernel_launch(void* const* d_in, const int* in_sizes, int n_in,
                              void* d_out, int out_size)
{
    const float* Q  = (const float*)d_in[0];
    const float* K  = (const float*)d_in[1];
    const float* V  = (const float*)d_in[2];
    const int* causal = (const int*)d_in[3];
    float* out = (float*)d_out;

    const int BH = in_sizes[0] / (N_SEQ * D);   // 32
    dim3 grid(N_SEQ / BQ, BH);
    dim3 block(THREADS);
    lorentz_attn_kernel<<<grid, block>>>(Q, K, V, causal, out);
}

// round 6
// speedup vs baseline: 3.3196x; 2.6420x over previous
#include <cuda_runtime.h>
#include <cuda_bf16.h>
#include <stdint.h>
#include <math.h>

// QuadraticLorentzAttention via mma.sync (HMMA bf16, sm_80+ path — the bench
// ptxas target is plain sm_100, no tcgen05).
// s = <qs,ks> - t_q t_k  (<= -1 on-hyperboloid) => no-max softmax with
// constant shift p = exp(s + 64) (cancels in normalization; avoids underflow).
// QK^T: bf16 hi/lo split, 3 passes, K-dim 80. PV: P bf16 (l summed from
// rounded P), V hi/lo split, 2 passes. O in fp32 mma accumulators.

namespace {
constexpr int N_SEQ = 2048;
constexpr int D     = 65;
constexpr int BQ    = 128;    // queries per CTA (8 warps x 16 rows)
constexpr int BK    = 64;     // keys per tile
constexpr int THREADS = 256;
constexpr float SHIFT = 64.0f;

// smem strides (bf16 elems) chosen for conflict-free ldmatrix (odd 16B count)
constexpr int QS = 88;   // 176B rows
constexpr int VS = 72;   // 144B rows
// byte offsets
constexpr uint32_t OFF_QH = 0;
constexpr uint32_t OFF_QL = OFF_QH + BQ * QS * 2;     // 22528
constexpr uint32_t OFF_KH = OFF_QL + BQ * QS * 2;     // 45056
constexpr uint32_t OFF_KL = OFF_KH + BK * QS * 2;     // 56320
constexpr uint32_t OFF_VH = OFF_KL + BK * QS * 2;     // 67584
constexpr uint32_t OFF_VL = OFF_VH + BK * VS * 2;     // 76800
constexpr uint32_t OFF_P  = OFF_VL + BK * VS * 2;     // 86016
constexpr uint32_t SMEM_TOTAL = OFF_P + BQ * VS * 2;  // 104448
}

__device__ __forceinline__ uint32_t smem_u32(const void* p) {
    uint32_t a;
    asm("{ .reg .u64 t; cvta.to.shared.u64 t, %1; cvt.u32.u64 %0, t; }" : "=r"(a) : "l"(p));
    return a;
}
__device__ __forceinline__ void ldm_x4(uint32_t* r, uint32_t a) {
    asm volatile("ldmatrix.sync.aligned.m8n8.x4.shared.b16 {%0,%1,%2,%3}, [%4];"
                 : "=r"(r[0]), "=r"(r[1]), "=r"(r[2]), "=r"(r[3]) : "r"(a) : "memory");
}
__device__ __forceinline__ void ldm_x2(uint32_t* r, uint32_t a) {
    asm volatile("ldmatrix.sync.aligned.m8n8.x2.shared.b16 {%0,%1}, [%2];"
                 : "=r"(r[0]), "=r"(r[1]) : "r"(a) : "memory");
}
__device__ __forceinline__ void ldm_x2t(uint32_t* r, uint32_t a) {
    asm volatile("ldmatrix.sync.aligned.m8n8.x2.trans.shared.b16 {%0,%1}, [%2];"
                 : "=r"(r[0]), "=r"(r[1]) : "r"(a) : "memory");
}
__device__ __forceinline__ void mma_bf16(float* c, const uint32_t* a, const uint32_t* b) {
    asm volatile("mma.sync.aligned.m16n8k16.row.col.f32.bf16.bf16.f32 "
                 "{%0,%1,%2,%3}, {%4,%5,%6,%7}, {%8,%9}, {%0,%1,%2,%3};"
                 : "+f"(c[0]), "+f"(c[1]), "+f"(c[2]), "+f"(c[3])
                 : "r"(a[0]), "r"(a[1]), "r"(a[2]), "r"(a[3]), "r"(b[0]), "r"(b[1]));
}
// split float pair into bf16x2 hi + bf16x2 residual lo (memory order: lo elem first)
__device__ __forceinline__ void split2(float a, float b, uint32_t& hi, uint32_t& lo) {
    __nv_bfloat16 ah = __float2bfloat16(a);
    __nv_bfloat16 bh = __float2bfloat16(b);
    __nv_bfloat16 al = __float2bfloat16(a - __bfloat162float(ah));
    __nv_bfloat16 bl = __float2bfloat16(b - __bfloat162float(bh));
    hi = ((uint32_t)__bfloat16_as_ushort(bh) << 16) | (uint32_t)__bfloat16_as_ushort(ah);
    lo = ((uint32_t)__bfloat16_as_ushort(bl) << 16) | (uint32_t)__bfloat16_as_ushort(al);
}
__device__ __forceinline__ uint32_t cvt_bf16x2(float lo, float hi) {
    uint32_t r;
    asm("cvt.rn.satfinite.bf16x2.f32 %0, %1, %2;" : "=r"(r) : "f"(hi), "f"(lo));
    return r;
}

extern __shared__ char smem_raw[];

__global__ void __launch_bounds__(THREADS)
lorentz_attn_mma(const float* __restrict__ Qg,
                 const float* __restrict__ Kg,
                 const float* __restrict__ Vg,
                 const int* __restrict__ causal_p,
                 float* __restrict__ Og)
{
    char* smem = smem_raw;
    const uint32_t sb = smem_u32(smem);
    const int t  = threadIdx.x;
    const int w  = t >> 5;          // warp 0..7, owns query rows w*16..w*16+15
    const int ln = t & 31;
    const int g  = ln >> 2;         // group (row within 8)
    const int tg = ln & 3;
    const int bh = blockIdx.y;
    const int q0 = (gridDim.x - 1 - blockIdx.x) * BQ;   // heavy causal tiles first
    const size_t base = (size_t)bh * N_SEQ * D;
    const int cz = *causal_p;

    // per-lane ldmatrix address components
    const int arow = (ln & 7) + ((ln >> 3) & 1) * 8;    // A-frag row offset
    const int adim = (ln >> 4) * 8;                     // A-frag col-block offset
    const int brow = ln & 7;                            // QK B-frag key offset
    const int bdim = ((ln >> 3) & 1) * 8;               // QK B-frag dim-block offset

    // ---- stage Q tile (once): dims 0..63 spatial, dim 64 = +t_q, 65..79 = 0 ----
    {
        const int r = t >> 1, h = t & 1;
        const float* qr = Qg + base + (size_t)(q0 + r) * D;
        #pragma unroll 4
        for (int d = 0; d < 32; d += 2) {
            uint32_t hi, lo;
            split2(qr[1 + 32*h + d], qr[2 + 32*h + d], hi, lo);
            const uint32_t off = 2u * (r * QS + 32*h + d);
            *(uint32_t*)(smem + OFF_QH + off) = hi;
            *(uint32_t*)(smem + OFF_QL + off) = lo;
        }
        if (h) {
            uint32_t hi, lo;
            split2(qr[0], 0.f, hi, lo);                 // +t_q at dim 64
            uint32_t off = 2u * (r * QS + 64);
            *(uint32_t*)(smem + OFF_QH + off) = hi;
            *(uint32_t*)(smem + OFF_QL + off) = lo;
            #pragma unroll
            for (int d2 = 66; d2 < 80; d2 += 2) {
                off = 2u * (r * QS + d2);
                *(uint32_t*)(smem + OFF_QH + off) = 0u;
                *(uint32_t*)(smem + OFF_QL + off) = 0u;
            }
        }
    }
    __syncthreads();

    // ---- Q fragments, register-resident across all tiles ----
    uint32_t qh[5][4], qlo[5][4];
    #pragma unroll
    for (int ks = 0; ks < 5; ks++) {
        const uint32_t ao = 2u * ((w*16 + arow) * QS + ks*16 + adim);
        ldm_x4(qh[ks],  sb + OFF_QH + ao);
        ldm_x4(qlo[ks], sb + OFF_QL + ao);
    }

    float O[8][4];
    #pragma unroll
    for (int i = 0; i < 8; i++)
        { O[i][0]=0.f; O[i][1]=0.f; O[i][2]=0.f; O[i][3]=0.f; }
    float la0 = 0.f, la1 = 0.f;     // per-lane partial row sums (16 keys each)

    const int rA = q0 + w*16 + g;   // this lane's query rows
    const int rB = rA + 8;
    const int ntiles = cz ? (q0 >> 6) + 2 : (N_SEQ / BK);

    for (int kt = 0; kt < ntiles; kt++) {
        const int k0 = kt * BK;
        __syncthreads();            // prior tile's K/V/P reads complete

        // ---- stage K (threads 0..127) / V (threads 128..255) ----
        {
            const int r = (t & 127) >> 1, h = t & 1;
            if (t < 128) {
                const float* kr = Kg + base + (size_t)(k0 + r) * D;
                #pragma unroll 4
                for (int d = 0; d < 32; d += 2) {
                    uint32_t hi, lo;
                    split2(kr[1 + 32*h + d], kr[2 + 32*h + d], hi, lo);
                    const uint32_t off = 2u * (r * QS + 32*h + d);
                    *(uint32_t*)(smem + OFF_KH + off) = hi;
                    *(uint32_t*)(smem + OFF_KL + off) = lo;
                }
                if (h) {
                    uint32_t hi, lo;
                    split2(-kr[0], 0.f, hi, lo);        // -t_k at dim 64
                    uint32_t off = 2u * (r * QS + 64);
                    *(uint32_t*)(smem + OFF_KH + off) = hi;
                    *(uint32_t*)(smem + OFF_KL + off) = lo;
                    #pragma unroll
                    for (int d2 = 66; d2 < 80; d2 += 2) {
                        off = 2u * (r * QS + d2);
                        *(uint32_t*)(smem + OFF_KH + off) = 0u;
                        *(uint32_t*)(smem + OFF_KL + off) = 0u;
                    }
                }
            } else {
                const float* vr = Vg + base + (size_t)(k0 + r) * D;
                #pragma unroll 4
                for (int d = 0; d < 32; d += 2) {
                    uint32_t hi, lo;
                    split2(vr[1 + 32*h + d], vr[2 + 32*h + d], hi, lo);
                    const uint32_t off = 2u * (r * VS + 32*h + d);
                    *(uint32_t*)(smem + OFF_VH + off) = hi;
                    *(uint32_t*)(smem + OFF_VL + off) = lo;
                }
            }
        }
        __syncthreads();

        const bool active = !cz || (q0 + w*16 + 15 >= k0);
        if (!active) continue;
        const bool maskT = cz && (k0 + BK - 1 > q0 + w*16);

        // ---- S = Q'K^T for 8 key n-blocks (pairs for ILP), softmax -> P smem ----
        #pragma unroll
        for (int nbp = 0; nbp < 4; nbp++) {
            const int nb0 = 2*nbp, nb1 = nb0 + 1;
            float s0[4] = {0.f,0.f,0.f,0.f};
            float s1[4] = {0.f,0.f,0.f,0.f};
            #pragma unroll
            for (int ks = 0; ks < 5; ks++) {
                uint32_t bh0[2], bl0[2], bh1[2], bl1[2];
                const uint32_t a0 = 2u * ((nb0*8 + brow) * QS + ks*16 + bdim);
                const uint32_t a1 = 2u * ((nb1*8 + brow) * QS + ks*16 + bdim);
                ldm_x2(bh0, sb + OFF_KH + a0);
                ldm_x2(bh1, sb + OFF_KH + a1);
                ldm_x2(bl0, sb + OFF_KL + a0);
                ldm_x2(bl1, sb + OFF_KL + a1);
                mma_bf16(s0, qh[ks], bh0);  mma_bf16(s1, qh[ks], bh1);
                mma_bf16(s0, qh[ks], bl0);  mma_bf16(s1, qh[ks], bl1);
                mma_bf16(s0, qlo[ks], bh0); mma_bf16(s1, qlo[ks], bh1);
            }
            #pragma unroll
            for (int e = 0; e < 2; e++) {
                const float* s = e ? s1 : s0;
                const int nb = e ? nb1 : nb0;
                float p0 = __expf(s[0] + SHIFT);
                float p1 = __expf(s[1] + SHIFT);
                float p2 = __expf(s[2] + SHIFT);
                float p3 = __expf(s[3] + SHIFT);
                if (maskT) {
                    const int kb = k0 + nb*8 + tg*2;
                    if (kb     > rA) p0 = 0.f;
                    if (kb + 1 > rA) p1 = 0.f;
                    if (kb     > rB) p2 = 0.f;
                    if (kb + 1 > rB) p3 = 0.f;
                }
                const uint32_t w01 = cvt_bf16x2(p0, p1);
                const uint32_t w23 = cvt_bf16x2(p2, p3);
                // l from ROUNDED weights so rounding cancels in normalization
                la0 += __uint_as_float(w01 << 16) + __uint_as_float(w01 & 0xffff0000u);
                la1 += __uint_as_float(w23 << 16) + __uint_as_float(w23 & 0xffff0000u);
                const uint32_t pc = 2u * (nb*8 + tg*2);
                *(uint32_t*)(smem + OFF_P + 2u*((w*16 + g    ) * VS) + pc) = w01;
                *(uint32_t*)(smem + OFF_P + 2u*((w*16 + g + 8) * VS) + pc) = w23;
            }
        }
        __syncwarp();

        // ---- O += P * (Vhi + Vlo) ----
        uint32_t pA[4][4];
        #pragma unroll
        for (int ks = 0; ks < 4; ks++)
            ldm_x4(pA[ks], sb + OFF_P + 2u*((w*16 + arow) * VS + ks*16 + adim));

        #pragma unroll
        for (int nbp = 0; nbp < 4; nbp++) {
            const int nb0 = 2*nbp, nb1 = nb0 + 1;
            #pragma unroll
            for (int ks = 0; ks < 4; ks++) {
                uint32_t vh0[2], vl0[2], vh1[2], vl1[2];
                const uint32_t vo = 2u * ((ks*16 + (ln & 15)) * VS);
                ldm_x2t(vh0, sb + OFF_VH + vo + 2u*(nb0*8));
                ldm_x2t(vh1, sb + OFF_VH + vo + 2u*(nb1*8));
                ldm_x2t(vl0, sb + OFF_VL + vo + 2u*(nb0*8));
                ldm_x2t(vl1, sb + OFF_VL + vo + 2u*(nb1*8));
                mma_bf16(O[nb0], pA[ks], vh0); mma_bf16(O[nb1], pA[ks], vh1);
                mma_bf16(O[nb0], pA[ks], vl0); mma_bf16(O[nb1], pA[ks], vl1);
            }
        }
    }

    // ---- epilogue: finish l, normalize, recompute time coord, store ----
    la0 += __shfl_xor_sync(0xffffffffu, la0, 1);
    la0 += __shfl_xor_sync(0xffffffffu, la0, 2);
    la1 += __shfl_xor_sync(0xffffffffu, la1, 1);
    la1 += __shfl_xor_sync(0xffffffffu, la1, 2);
    const float il0 = 1.0f / la0;
    const float il1 = 1.0f / la1;

    float y[8][4];
    float ss0 = 0.f, ss1 = 0.f;
    #pragma unroll
    for (int nb = 0; nb < 8; nb++) {
        y[nb][0] = O[nb][0] * il0;  y[nb][1] = O[nb][1] * il0;
        y[nb][2] = O[nb][2] * il1;  y[nb][3] = O[nb][3] * il1;
        ss0 += y[nb][0]*y[nb][0] + y[nb][1]*y[nb][1];
        ss1 += y[nb][2]*y[nb][2] + y[nb][3]*y[nb][3];
    }
    ss0 += __shfl_xor_sync(0xffffffffu, ss0, 1);
    ss0 += __shfl_xor_sync(0xffffffffu, ss0, 2);
    ss1 += __shfl_xor_sync(0xffffffffu, ss1, 1);
    ss1 += __shfl_xor_sync(0xffffffffu, ss1, 2);
    const float tc0 = sqrtf(ss0 + 1.0f);
    const float tc1 = sqrtf(ss1 + 1.0f);

    float* o0 = Og + base + (size_t)rA * D;
    float* o1 = Og + base + (size_t)rB * D;
    #pragma unroll
    for (int nb = 0; nb < 8; nb++) {
        const int d = nb*8 + tg*2;
        o0[1 + d] = y[nb][0];  o0[2 + d] = y[nb][1];
        o1[1 + d] = y[nb][2];  o1[2 + d] = y[nb][3];
    }
    if (tg == 0) { o0[0] = tc0; o1[0] = tc1; }
}

extern "C" void kernel_launch(void* const* d_in, const int* in_sizes, int n_in,
                              void* d_out, int out_size)
{
    const float* Q  = (const float*)d_in[0];
    const float* K  = (const float*)d_in[1];
    const float* V  = (const float*)d_in[2];
    const int* causal = (const int*)d_in[3];
    float* out = (float*)d_out;

    cudaFuncSetAttribute(lorentz_attn_mma,
                         cudaFuncAttributeMaxDynamicSharedMemorySize, SMEM_TOTAL);

    const int BH = in_sizes[0] / (N_SEQ * D);   // 32
    dim3 grid(N_SEQ / BQ, BH);
    dim3 block(THREADS);
    lorentz_attn_mma<<<grid, block, SMEM_TOTAL>>>(Q, K, V, causal, out);
}

// round 10
// speedup vs baseline: 5.2952x; 1.5951x over previous
#include <cuda_runtime.h>
#include <cuda_bf16.h>
#include <stdint.h>
#include <math.h>

// QuadraticLorentzAttention via mma.sync bf16 (plain-sm_100-safe).
// s = <qs,ks> - t_q t_k <= -1 on-hyperboloid => no-max softmax, p=exp(s+64).
// R6-R9: (1) P passes QK->PV in registers (C-frag == A-frag layout),
//        (2) global bf16 hi/lo precompute + cp.async double-buffered staging,
//        (3) x4 ldmatrix merging. (R9: resubmit after repeated broker failures.)

namespace {
constexpr int N_SEQ = 2048;
constexpr int D     = 65;
constexpr int BQ    = 128;    // 8 warps x 16 query rows
constexpr int BK    = 64;
constexpr int THREADS = 256;
constexpr int BHMAX = 32;
constexpr float SHIFT = 64.0f;

// smem element strides (bf16): rows 176B / 144B, odd 16B count -> conflict-free
constexpr int QS = 88;
// smem byte offsets. Q region (45056B) is reused as K/V buffer 1 after
// Q fragments move to registers.
constexpr uint32_t OFF_QH = 0;
constexpr uint32_t OFF_QL = 22528;
constexpr uint32_t SMEM_TOTAL = 86016;
}

// buffer base offsets (buf 0 lives above Q; buf 1 overlays dead Q region)
__device__ __forceinline__ uint32_t kh_off(int b) { return b ? 0u     : 45056u; }
__device__ __forceinline__ uint32_t kl_off(int b) { return b ? 11264u : 56320u; }
__device__ __forceinline__ uint32_t vh_off(int b) { return b ? 22528u : 67584u; }
__device__ __forceinline__ uint32_t vl_off(int b) { return b ? 31744u : 76800u; }

// global bf16 hi/lo scratch (written by prep kernel each launch)
__device__ __align__(128) __nv_bfloat16 g_qh[(size_t)BHMAX * N_SEQ * 80];
__device__ __align__(128) __nv_bfloat16 g_ql[(size_t)BHMAX * N_SEQ * 80];
__device__ __align__(128) __nv_bfloat16 g_kh[(size_t)BHMAX * N_SEQ * 80];
__device__ __align__(128) __nv_bfloat16 g_kl[(size_t)BHMAX * N_SEQ * 80];
__device__ __align__(128) __nv_bfloat16 g_vh[(size_t)BHMAX * N_SEQ * 64];
__device__ __align__(128) __nv_bfloat16 g_vl[(size_t)BHMAX * N_SEQ * 64];

__device__ __forceinline__ uint32_t smem_u32(const void* p) {
    uint32_t a;
    asm("{ .reg .u64 t; cvta.to.shared.u64 t, %1; cvt.u32.u64 %0, t; }" : "=r"(a) : "l"(p));
    return a;
}
__device__ __forceinline__ void ldm_x4(uint32_t* r, uint32_t a) {
    asm volatile("ldmatrix.sync.aligned.m8n8.x4.shared.b16 {%0,%1,%2,%3}, [%4];"
                 : "=r"(r[0]), "=r"(r[1]), "=r"(r[2]), "=r"(r[3]) : "r"(a) : "memory");
}
__device__ __forceinline__ void ldm_x4t(uint32_t* r, uint32_t a) {
    asm volatile("ldmatrix.sync.aligned.m8n8.x4.trans.shared.b16 {%0,%1,%2,%3}, [%4];"
                 : "=r"(r[0]), "=r"(r[1]), "=r"(r[2]), "=r"(r[3]) : "r"(a) : "memory");
}
__device__ __forceinline__ void mma_bf16(float* c, const uint32_t* a, const uint32_t* b) {
    asm volatile("mma.sync.aligned.m16n8k16.row.col.f32.bf16.bf16.f32 "
                 "{%0,%1,%2,%3}, {%4,%5,%6,%7}, {%8,%9}, {%0,%1,%2,%3};"
                 : "+f"(c[0]), "+f"(c[1]), "+f"(c[2]), "+f"(c[3])
                 : "r"(a[0]), "r"(a[1]), "r"(a[2]), "r"(a[3]), "r"(b[0]), "r"(b[1]));
}
__device__ __forceinline__ uint32_t cvt_bf16x2(float lo, float hi) {
    uint32_t r;
    asm("cvt.rn.satfinite.bf16x2.f32 %0, %1, %2;" : "=r"(r) : "f"(hi), "f"(lo));
    return r;
}
__device__ __forceinline__ void cpa16(uint32_t dst, const void* src) {
    asm volatile("cp.async.cg.shared.global [%0], [%1], 16;" :: "r"(dst), "l"(src) : "memory");
}
#define CP_COMMIT() asm volatile("cp.async.commit_group;" ::: "memory")
#define CP_WAIT1()  asm volatile("cp.async.wait_group 1;" ::: "memory")

// ---------------- prep: fp32 -> bf16 hi/lo global layout ----------------
__global__ void __launch_bounds__(256)
prep_kernel(const float* __restrict__ Q, const float* __restrict__ K,
            const float* __restrict__ V, int BH)
{
    const int row = blockIdx.x * 8 + (threadIdx.x >> 5);
    const int ln  = threadIdx.x & 31;
    if (row >= BH * N_SEQ) return;
    const float* q = Q + (size_t)row * D;
    const float* k = K + (size_t)row * D;
    const float* v = V + (size_t)row * D;
    const size_t o80 = (size_t)row * 80, o64 = (size_t)row * 64;

    #pragma unroll
    for (int h = 0; h < 2; h++) {
        const int d = ln + 32 * h;
        const float qv = q[1 + d], kv = k[1 + d], vv = v[1 + d];
        __nv_bfloat16 x;
        x = __float2bfloat16(qv); g_qh[o80 + d] = x; g_ql[o80 + d] = __float2bfloat16(qv - __bfloat162float(x));
        x = __float2bfloat16(kv); g_kh[o80 + d] = x; g_kl[o80 + d] = __float2bfloat16(kv - __bfloat162float(x));
        x = __float2bfloat16(vv); g_vh[o64 + d] = x; g_vl[o64 + d] = __float2bfloat16(vv - __bfloat162float(x));
    }
    if (ln == 0) {
        const float tq = q[0];
        __nv_bfloat16 h = __float2bfloat16(tq);
        g_qh[o80 + 64] = h; g_ql[o80 + 64] = __float2bfloat16(tq - __bfloat162float(h));
        const float tk = -k[0];
        h = __float2bfloat16(tk);
        g_kh[o80 + 64] = h; g_kl[o80 + 64] = __float2bfloat16(tk - __bfloat162float(h));
    } else if (ln < 16) {
        const __nv_bfloat16 z = __float2bfloat16(0.f);
        g_qh[o80 + 64 + ln] = z; g_ql[o80 + 64 + ln] = z;
        g_kh[o80 + 64 + ln] = z; g_kl[o80 + 64 + ln] = z;
    }
}

// ---------------- main attention kernel ----------------
extern __shared__ char smem_raw[];

__device__ __forceinline__ void issue_kv(uint32_t sb, int buf, int kbase, int t) {
    const uint32_t khd = sb + kh_off(buf), kld = sb + kl_off(buf);
    const uint32_t vhd = sb + vh_off(buf), vld = sb + vl_off(buf);
    #pragma unroll
    for (int it = 0; it < 9; it++) {
        const int c = t + it * 256;
        if (c < 1280) {
            const int half = c >= 640;
            const int cc = c - half * 640;
            const int row = cc / 10, ch = cc - row * 10;
            const __nv_bfloat16* src = (half ? g_kl : g_kh) + ((size_t)(kbase + row)) * 80 + ch * 8;
            cpa16((half ? kld : khd) + row * 176 + ch * 16, src);
        } else {
            const int cc0 = c - 1280;
            const int half = cc0 >= 512;
            const int cc = cc0 - half * 512;
            const int row = cc >> 3, ch = cc & 7;
            const __nv_bfloat16* src = (half ? g_vl : g_vh) + ((size_t)(kbase + row)) * 64 + ch * 8;
            cpa16((half ? vld : vhd) + row * 144 + ch * 16, src);
        }
    }
}

__global__ void __launch_bounds__(THREADS, 2)
lorentz_attn_mma(const int* __restrict__ causal_p, float* __restrict__ Og)
{
    const uint32_t sb = smem_u32(smem_raw);
    const int t  = threadIdx.x;
    const int w  = t >> 5;
    const int ln = t & 31;
    const int g  = ln >> 2;
    const int tg = ln & 3;
    const int bh = blockIdx.y;
    const int q0 = (gridDim.x - 1 - blockIdx.x) * BQ;   // heavy causal tiles first
    const int cz = *causal_p;
    const size_t obase = (size_t)bh * N_SEQ * D;

    const int arow = (ln & 7) + ((ln >> 3) & 1) * 8;    // A-frag addressing
    const int adim = (ln >> 4) * 8;
    const int ntiles = cz ? (q0 >> 6) + 2 : (N_SEQ / BK);
    const int qbase = bh * N_SEQ + q0;
    const int kvbase = bh * N_SEQ;

    // ---- stage Q (group Gq), then K/V tile 0 (G0) ----
    #pragma unroll
    for (int it = 0; it < 10; it++) {
        const int c = t + it * 256;
        const int half = c >= 1280;
        const int cc = c - half * 1280;
        const int row = cc / 10, ch = cc - row * 10;
        const __nv_bfloat16* src = (half ? g_ql : g_qh) + ((size_t)(qbase + row)) * 80 + ch * 8;
        cpa16(sb + (half ? OFF_QL : OFF_QH) + row * 176 + ch * 16, src);
    }
    CP_COMMIT();
    issue_kv(sb, 0, kvbase, t);
    CP_COMMIT();
    CP_WAIT1();            // Gq done (G0 may pend)
    __syncthreads();

    // ---- Q fragments to registers ----
    uint32_t qh[5][4], qlo[5][4];
    #pragma unroll
    for (int ks = 0; ks < 5; ks++) {
        const uint32_t ao = 2u * ((w * 16 + arow) * QS + ks * 16 + adim);
        ldm_x4(qh[ks],  sb + OFF_QH + ao);
        ldm_x4(qlo[ks], sb + OFF_QL + ao);
    }
    __syncthreads();       // Q region free -> becomes buffer 1

    if (ntiles > 1) issue_kv(sb, 1, kvbase + BK, t);
    CP_COMMIT();           // G1

    float O[8][4];
    #pragma unroll
    for (int i = 0; i < 8; i++)
        { O[i][0]=0.f; O[i][1]=0.f; O[i][2]=0.f; O[i][3]=0.f; }
    float la0 = 0.f, la1 = 0.f;
    const int rA = q0 + w * 16 + g;
    const int rB = rA + 8;

    for (int kt = 0; kt < ntiles; kt++) {
        const int k0 = kt * BK;
        const int buf = kt & 1;
        CP_WAIT1();        // tile kt ready (kt+1 may pend)
        __syncthreads();

        const bool active = !cz || (q0 + w * 16 + 15 >= k0);
        if (active) {
            const bool maskT = cz && (k0 + BK - 1 > q0 + w * 16);
            const uint32_t khO = sb + kh_off(buf), klO = sb + kl_off(buf);
            const uint32_t vhO = sb + vh_off(buf), vlO = sb + vl_off(buf);

            // ---- S = Q'K^T (3 bf16 passes), softmax -> pa regs ----
            uint32_t pa[4][4];
            const int keyb = (ln >> 4) * 8 + (ln & 7);      // + nbp*16
            const int dsel = ((ln >> 3) & 1) * 8;
            #pragma unroll
            for (int nbp = 0; nbp < 4; nbp++) {
                float s0[4] = {0.f,0.f,0.f,0.f};
                float s1[4] = {0.f,0.f,0.f,0.f};
                const uint32_t krow = (uint32_t)(nbp * 16 + keyb) * 176u;
                #pragma unroll
                for (int ks = 0; ks < 5; ks++) {
                    uint32_t b4[4], l4[4];
                    const uint32_t doff = (uint32_t)(ks * 16 + dsel) * 2u;
                    ldm_x4(b4, khO + krow + doff);
                    ldm_x4(l4, klO + krow + doff);
                    mma_bf16(s0, qh[ks],  b4);     mma_bf16(s1, qh[ks],  b4 + 2);
                    mma_bf16(s0, qh[ks],  l4);     mma_bf16(s1, qh[ks],  l4 + 2);
                    mma_bf16(s0, qlo[ks], b4);     mma_bf16(s1, qlo[ks], b4 + 2);
                }
                float p00 = __expf(s0[0] + SHIFT), p01 = __expf(s0[1] + SHIFT);
                float p02 = __expf(s0[2] + SHIFT), p03 = __expf(s0[3] + SHIFT);
                float p10 = __expf(s1[0] + SHIFT), p11 = __expf(s1[1] + SHIFT);
                float p12 = __expf(s1[2] + SHIFT), p13 = __expf(s1[3] + SHIFT);
                if (maskT) {
                    const int kb0 = k0 + nbp * 16 + tg * 2;
                    const int kb1 = kb0 + 8;
                    if (kb0     > rA) p00 = 0.f;
                    if (kb0 + 1 > rA) p01 = 0.f;
                    if (kb0     > rB) p02 = 0.f;
                    if (kb0 + 1 > rB) p03 = 0.f;
                    if (kb1     > rA) p10 = 0.f;
                    if (kb1 + 1 > rA) p11 = 0.f;
                    if (kb1     > rB) p12 = 0.f;
                    if (kb1 + 1 > rB) p13 = 0.f;
                }
                // C-frag == PV A-frag layout: pack directly
                const uint32_t a0 = cvt_bf16x2(p00, p01);
                const uint32_t a1 = cvt_bf16x2(p02, p03);
                const uint32_t a2 = cvt_bf16x2(p10, p11);
                const uint32_t a3 = cvt_bf16x2(p12, p13);
                pa[nbp][0] = a0; pa[nbp][1] = a1; pa[nbp][2] = a2; pa[nbp][3] = a3;
                // l from ROUNDED weights so rounding cancels in normalization
                la0 += __uint_as_float(a0 << 16) + __uint_as_float(a0 & 0xffff0000u)
                     + __uint_as_float(a2 << 16) + __uint_as_float(a2 & 0xffff0000u);
                la1 += __uint_as_float(a1 << 16) + __uint_as_float(a1 & 0xffff0000u)
                     + __uint_as_float(a3 << 16) + __uint_as_float(a3 & 0xffff0000u);
            }

            // ---- O += P * (Vhi + Vlo) ----
            const int vr = ln & 15;
            const int vcb = (ln >> 4) * 8;
            #pragma unroll
            for (int i = 0; i < 4; i++) {             // key blocks
                const uint32_t vrow = (uint32_t)(i * 16 + vr) * 144u;
                #pragma unroll
                for (int np = 0; np < 4; np++) {      // output dim pairs
                    uint32_t vh4[4], vl4[4];
                    const uint32_t off = vrow + (uint32_t)(np * 16 + vcb) * 2u;
                    ldm_x4t(vh4, vhO + off);
                    ldm_x4t(vl4, vlO + off);
                    mma_bf16(O[2*np],     pa[i], vh4);
                    mma_bf16(O[2*np + 1], pa[i], vh4 + 2);
                    mma_bf16(O[2*np],     pa[i], vl4);
                    mma_bf16(O[2*np + 1], pa[i], vl4 + 2);
                }
            }
        }

        __syncthreads();   // all warps done reading buf
        if (kt + 2 < ntiles) issue_kv(sb, buf, kvbase + (kt + 2) * BK, t);
        CP_COMMIT();
    }

    // ---- epilogue ----
    la0 += __shfl_xor_sync(0xffffffffu, la0, 1);
    la0 += __shfl_xor_sync(0xffffffffu, la0, 2);
    la1 += __shfl_xor_sync(0xffffffffu, la1, 1);
    la1 += __shfl_xor_sync(0xffffffffu, la1, 2);
    const float il0 = 1.0f / la0;
    const float il1 = 1.0f / la1;

    float y[8][4];
    float ss0 = 0.f, ss1 = 0.f;
    #pragma unroll
    for (int nb = 0; nb < 8; nb++) {
        y[nb][0] = O[nb][0] * il0;  y[nb][1] = O[nb][1] * il0;
        y[nb][2] = O[nb][2] * il1;  y[nb][3] = O[nb][3] * il1;
        ss0 += y[nb][0]*y[nb][0] + y[nb][1]*y[nb][1];
        ss1 += y[nb][2]*y[nb][2] + y[nb][3]*y[nb][3];
    }
    ss0 += __shfl_xor_sync(0xffffffffu, ss0, 1);
    ss0 += __shfl_xor_sync(0xffffffffu, ss0, 2);
    ss1 += __shfl_xor_sync(0xffffffffu, ss1, 1);
    ss1 += __shfl_xor_sync(0xffffffffu, ss1, 2);
    const float tc0 = sqrtf(ss0 + 1.0f);
    const float tc1 = sqrtf(ss1 + 1.0f);

    float* o0 = Og + obase + (size_t)rA * D;
    float* o1 = Og + obase + (size_t)rB * D;
    #pragma unroll
    for (int nb = 0; nb < 8; nb++) {
        const int d = nb * 8 + tg * 2;
        o0[1 + d] = y[nb][0];  o0[2 + d] = y[nb][1];
        o1[1 + d] = y[nb][2];  o1[2 + d] = y[nb][3];
    }
    if (tg == 0) { o0[0] = tc0; o1[0] = tc1; }
}

extern "C" void kernel_launch(void* const* d_in, const int* in_sizes, int n_in,
                              void* d_out, int out_size)
{
    const float* Q  = (const float*)d_in[0];
    const float* K  = (const float*)d_in[1];
    const float* V  = (const float*)d_in[2];
    const int* causal = (const int*)d_in[3];
    float* out = (float*)d_out;

    const int BH = in_sizes[0] / (N_SEQ * D);   // 32

    prep_kernel<<<BH * N_SEQ / 8, 256>>>(Q, K, V, BH);

    cudaFuncSetAttribute(lorentz_attn_mma,
                         cudaFuncAttributeMaxDynamicSharedMemorySize, SMEM_TOTAL);
    dim3 grid(N_SEQ / BQ, BH);
    lorentz_attn_mma<<<grid, THREADS, SMEM_TOTAL>>>(causal, out);
}